// round 1
// baseline (speedup 1.0000x reference)
#include <cuda_runtime.h>
#include <cstddef>

// HelixMemory: output (8, 2558, 2048) f32.
//  rows 510..2557  : copy of memory rows 512..2557 then inputs rows 0..1
//  rows 0..509     : hierarchical pair-averages of memory rows 1024..1535
//
// Level definitions (per batch b, column d), src[r] = memory[b][1024+r][d], r in [0,512):
//   L_0[i] = (src[2i]+src[2i+1])/2                      (256 entries, window 2)
//   L_k[i] = (L_{k-1}[2i]+L_{k-1}[2i+1])/2              (2^(8-k) entries, window 2^(k+1))
// Output mapping:
//   L_0[i], i>=128              -> row 126+i                  (rows 254..381)
//   L_k[i], k=1..8              -> row 3*2^(8-k)-2 + i
//   L_k[i], k=1..7, i>=2^(7-k)  -> row 2^(8-k)-2 + i-2^(7-k)
// Kernel 1 computes levels 0..6 (each 128-row subtree is independent).
// Kernel 2 derives L_7 (rows 4,5 and 0) and L_8 (row 1) from rows 10..13 (= L_6).

#define DCOLS 2048
#define MROWS 2558
#define POOL_BLOCKS 256
#define NTHREADS 256
#define COPY_F4 (8u * 2048u * 512u) /* 8,388,608 float4 */

__global__ void __launch_bounds__(NTHREADS) helix_main(
    const float4* __restrict__ mem4,
    const float4* __restrict__ inp4,
    const float*  __restrict__ mem,
    float*        __restrict__ out,
    float4*       __restrict__ out4)
{
    int bx = blockIdx.x;
    if (bx < POOL_BLOCKS) {
        // ---- pooling role: thread = (batch, subtree, column) ----
        int p  = bx * NTHREADS + threadIdx.x;   // 0..65535
        int d  = p & (DCOLS - 1);
        int bs = p >> 11;                       // 0..31
        int b  = bs >> 2;
        int s  = bs & 3;                        // subtree: rows [128s, 128s+128)

        const float* src  = mem + ((size_t)b * MROWS + 1024 + 128 * s) * DCOLS + d;
        float*       outb = out + (size_t)b * MROWS * DCOLS + d;

        float acc[7];
        #pragma unroll
        for (int l = 0; l < 7; ++l) acc[l] = 0.0f;

        #pragma unroll 4
        for (int rr = 0; rr < 128; ++rr) {
            float v = __ldg(src + (size_t)rr * DCOLS);
            int   r = s * 128 + rr;             // global row index in [0,512)
            #pragma unroll
            for (int l = 0; l < 7; ++l) {
                acc[l] += v;
                if (((r + 1) & ((2 << l) - 1)) != 0) break;   // window incomplete
                v = acc[l] * 0.5f;
                acc[l] = 0.0f;
                int i = r >> (l + 1);
                if (l == 0) {
                    if (i >= 128) outb[(size_t)(126 + i) * DCOLS] = v;
                } else {
                    int half = 256 >> l;        // 2^(8-l)
                    outb[(size_t)(3 * half - 2 + i) * DCOLS] = v;
                    if (i >= (half >> 1))
                        outb[(size_t)(half - 2 + i - (half >> 1)) * DCOLS] = v;
                }
            }
        }
    } else {
        // ---- copy role: one float4 per thread ----
        unsigned t = (unsigned)(bx - POOL_BLOCKS) * NTHREADS + threadIdx.x;
        if (t >= COPY_F4) return;
        unsigned b    = t >> 20;                 // 2048 rows * 512 f4 per batch
        unsigned rem  = t & 1048575u;
        unsigned row  = rem >> 9;                // 0..2047
        unsigned c4   = rem & 511u;
        unsigned srow = 512u + row;              // source row in new_memory
        float4 v;
        if (srow < (unsigned)MROWS)
            v = mem4[(size_t)b * (MROWS * 512) + (size_t)srow * 512 + c4];
        else
            v = inp4[(size_t)b * (1024 * 512) + (size_t)(srow - MROWS) * 512 + c4];
        out4[(size_t)b * (MROWS * 512) + (size_t)(510 + row) * 512 + c4] = v;
    }
}

__global__ void __launch_bounds__(NTHREADS) helix_fixup(float* __restrict__ out)
{
    int t = blockIdx.x * NTHREADS + threadIdx.x;  // 16384 threads
    int d = t & (DCOLS - 1);
    int b = t >> 11;
    float* outb = out + (size_t)b * MROWS * DCOLS + d;
    // rows 10..13 hold L_6[0..3]
    float a0 = outb[(size_t)10 * DCOLS];
    float a1 = outb[(size_t)11 * DCOLS];
    float a2 = outb[(size_t)12 * DCOLS];
    float a3 = outb[(size_t)13 * DCOLS];
    float l70 = 0.5f * (a0 + a1);   // L_7[0]
    float l71 = 0.5f * (a2 + a3);   // L_7[1]
    outb[(size_t)4 * DCOLS] = l70;  // part_7 second half
    outb[(size_t)5 * DCOLS] = l71;
    outb[0]                  = l71; // part_8 first half (L_7 second half)
    outb[(size_t)1 * DCOLS]  = 0.5f * (l70 + l71); // L_8
}

extern "C" void kernel_launch(void* const* d_in, const int* in_sizes, int n_in,
                              void* d_out, int out_size)
{
    // Identify tensors by element count (inputs: 8*1024*2048; memory: 8*2558*2048).
    const float* inputs = (const float*)d_in[0];
    const float* memory = (const float*)d_in[1];
    if (n_in >= 2 && in_sizes[0] > in_sizes[1]) {
        memory = (const float*)d_in[0];
        inputs = (const float*)d_in[1];
    }
    float* out = (float*)d_out;

    unsigned copy_blocks = (COPY_F4 + NTHREADS - 1) / NTHREADS;  // 32768
    helix_main<<<POOL_BLOCKS + copy_blocks, NTHREADS>>>(
        (const float4*)memory, (const float4*)inputs, memory, out, (float4*)out);
    helix_fixup<<<(8 * DCOLS) / NTHREADS, NTHREADS>>>(out);
}